// round 16
// baseline (speedup 1.0000x reference)
#include <cuda_runtime.h>
#include <cuda_bf16.h>
#include <math.h>

#define IMG 224
#define HALF 112
#define OFF 56.0f
#define TL_BASE 38
#define TL_RANGE 18.0f
#define RPB 28           // output rows per block -> 8 chunks x 256 = 2048 blocks (1.73 waves)
#define THREADS 224      // one thread per output column
#define CHS (IMG * IMG)  // channel stride

__device__ __forceinline__ float mask1d(float v, float t, float l) {
    float z1 = 10.0f * (v - t + l);
    float z2 = 10.0f * (v - t - l);
    float s1 = 1.0f / (1.0f + __expf(-z1));
    float s2 = 1.0f / (1.0f + __expf(-z2));
    return s1 - s2;
}

__global__ __launch_bounds__(THREADS, 8)
void attention_crop_kernel(const float* __restrict__ apn,
                           const float* __restrict__ in,
                           float* __restrict__ out) {
    const int b   = blockIdx.y;
    const int tid = threadIdx.x;

    // Per-batch crop params
    const float a0p = __ldg(&apn[b * 3 + 0]);
    const float a1p = __ldg(&apn[b * 3 + 1]);
    const float a2p = __ldg(&apn[b * 3 + 2]);
    const int tx = HALF + (int)truncf(a0p * OFF + 0.5f);
    const int ty = HALF + (int)truncf(a1p * OFF + 0.5f);
    const int tl = TL_BASE + (int)truncf((a2p + 1.0f) * 0.5f * TL_RANGE);
    const int in_size = 2 * tl;
    const float scale = (float)in_size * (1.0f / 224.0f);
    const float txf = (float)tx, tyf = (float)ty, tlf = (float)tl;

    // Column coefficients for col = tid (registers)
    float srcc = fmaxf((tid + 0.5f) * scale - 0.5f, 0.0f);
    int   ci0  = (int)srcc;
    float wc   = srcc - (float)ci0;
    int   ci1  = min(ci0 + 1, in_size - 1);
    const int   c0  = (ty - tl) + ci0;
    const int   c1  = (ty - tl) + ci1;
    const float a0c = (1.0f - wc) * mask1d((float)c0, tyf, tlf);
    const float a1c = wc          * mask1d((float)c1, tyf, tlf);

    // Source-row window for this block (uniform across threads)
    const int rb = blockIdx.x * RPB;
    const int i_first = (int)fmaxf((rb + 0.5f) * scale - 0.5f, 0.0f);
    const int abs_first = (tx - tl) + i_first;
    const int i_last_lo = (int)fmaxf((rb + RPB - 1 + 0.5f) * scale - 0.5f, 0.0f);
    const int i_last    = min(i_last_lo + 1, in_size - 1);
    const int nrows     = i_last - i_first + 1;   // <= 17

    // Packed per-row table: (q0 bits, q1 bits, w0, w1) — one LDS.128 broadcast/row
    __shared__ __align__(16) float4 s_tab[RPB];
    if (tid < RPB) {
        const int r = rb + tid;
        float src = fmaxf((r + 0.5f) * scale - 0.5f, 0.0f);
        int   i0  = (int)src;
        float wr  = src - (float)i0;
        int   i1  = min(i0 + 1, in_size - 1);
        const float r0a = (float)((tx - tl) + i0);
        const float r1a = (float)((tx - tl) + i1);
        s_tab[tid] = make_float4(__int_as_float(i0 - i_first),
                                 __int_as_float(i1 - i_first),
                                 (1.0f - wr) * mask1d(r0a, txf, tlf),
                                 wr          * mask1d(r1a, txf, tlf));
    }
    __syncthreads();

    const float* __restrict__ inb  = in  + (size_t)b * (3 * CHS);
    float*       __restrict__ outb = out + (size_t)b * (3 * CHS);

    const float* p0 = inb + abs_first * IMG + c0;
    const float* p1 = inb + abs_first * IMG + c1;
    float*       ob = outb + rb * IMG + tid;

    // Triple-buffered register roll over source rows; 3 channels in parallel
    // (6 batched LDGs per new source row). All control flow is block-uniform.
    float va[3], vb[3], vc[3];
    #pragma unroll
    for (int ch = 0; ch < 3; ch++)
        va[ch] = fmaf(a0c, __ldg(p0 + ch * CHS), a1c * __ldg(p1 + ch * CHS));
    if (nrows > 1) {
        #pragma unroll
        for (int ch = 0; ch < 3; ch++)
            vb[ch] = fmaf(a0c, __ldg(p0 + ch * CHS + IMG), a1c * __ldg(p1 + ch * CHS + IMG));
    } else {
        #pragma unroll
        for (int ch = 0; ch < 3; ch++) vb[ch] = va[ch];
    }
    if (nrows > 2) {
        #pragma unroll
        for (int ch = 0; ch < 3; ch++)
            vc[ch] = fmaf(a0c, __ldg(p0 + ch * CHS + 2 * IMG), a1c * __ldg(p1 + ch * CHS + 2 * IMG));
    } else {
        #pragma unroll
        for (int ch = 0; ch < 3; ch++) vc[ch] = vb[ch];
    }

    int q = 0;
    #pragma unroll
    for (int r = 0; r < RPB; r++) {
        const float4 t  = s_tab[r];
        const int    q0 = __float_as_int(t.x);
        const int    q1 = __float_as_int(t.y);

        if (q0 != q) {                       // advance exactly one source row
            #pragma unroll
            for (int ch = 0; ch < 3; ch++) { va[ch] = vb[ch]; vb[ch] = vc[ch]; }
            if (q0 + 2 < nrows) {            // prefetch one row ahead
                const int o = (q0 + 2) * IMG;
                #pragma unroll
                for (int ch = 0; ch < 3; ch++)
                    vc[ch] = fmaf(a0c, __ldg(p0 + ch * CHS + o),
                                  a1c * __ldg(p1 + ch * CHS + o));
            }
            q = q0;
        }

        const bool two = (q1 != q0);         // uniform; false only at clamp edge
        #pragma unroll
        for (int ch = 0; ch < 3; ch++) {
            const float v1 = two ? vb[ch] : va[ch];
            ob[ch * CHS + r * IMG] = fmaf(t.z, va[ch], t.w * v1);
        }
    }
}

extern "C" void kernel_launch(void* const* d_in, const int* in_sizes, int n_in,
                              void* d_out, int out_size) {
    const float* apn = (const float*)d_in[0];   // [256, 3]
    const float* in  = (const float*)d_in[1];   // [256, 3, 224, 224]
    float* out = (float*)d_out;                 // [256, 3, 224, 224]

    dim3 grid(IMG / RPB, 256);                  // (8 row-chunks, B)
    attention_crop_kernel<<<grid, THREADS>>>(apn, in, out);
}

// round 17
// speedup vs baseline: 1.1653x; 1.1653x over previous
#include <cuda_runtime.h>
#include <cuda_bf16.h>
#include <math.h>

#define IMG 224
#define HALF 112
#define OFF 56.0f
#define TL_BASE 38
#define TL_RANGE 18.0f
#define RPB 16           // output rows per block
#define THREADS 224      // one thread per output column
#define CHS (IMG * IMG)  // channel stride

__device__ __forceinline__ float mask1d(float v, float t, float l) {
    float z1 = 10.0f * (v - t + l);
    float z2 = 10.0f * (v - t - l);
    float s1 = 1.0f / (1.0f + __expf(-z1));
    float s2 = 1.0f / (1.0f + __expf(-z2));
    return s1 - s2;
}

__global__ __launch_bounds__(THREADS, 9)
void attention_crop_kernel(const float* __restrict__ apn,
                           const float* __restrict__ in,
                           float* __restrict__ out) {
    const int b   = blockIdx.y;
    const int tid = threadIdx.x;

    // Per-batch crop params
    const float a0p = __ldg(&apn[b * 3 + 0]);
    const float a1p = __ldg(&apn[b * 3 + 1]);
    const float a2p = __ldg(&apn[b * 3 + 2]);
    const int tx = HALF + (int)truncf(a0p * OFF + 0.5f);
    const int ty = HALF + (int)truncf(a1p * OFF + 0.5f);
    const int tl = TL_BASE + (int)truncf((a2p + 1.0f) * 0.5f * TL_RANGE);
    const int in_size = 2 * tl;
    const float scale = (float)in_size * (1.0f / 224.0f);
    const float txf = (float)tx, tyf = (float)ty, tlf = (float)tl;

    // Column coefficients for col = tid (registers)
    float srcc = fmaxf((tid + 0.5f) * scale - 0.5f, 0.0f);
    int   ci0  = (int)srcc;
    float wc   = srcc - (float)ci0;
    int   ci1  = min(ci0 + 1, in_size - 1);
    const int   c0  = (ty - tl) + ci0;
    const int   c1  = (ty - tl) + ci1;
    const float a0c = (1.0f - wc) * mask1d((float)c0, tyf, tlf);
    const float a1c = wc          * mask1d((float)c1, tyf, tlf);

    // Source-row window for this block (uniform across threads)
    const int rb = blockIdx.x * RPB;
    const int i_first = (int)fmaxf((rb + 0.5f) * scale - 0.5f, 0.0f);
    const int abs_first = (tx - tl) + i_first;
    const int i_last_lo = (int)fmaxf((rb + RPB - 1 + 0.5f) * scale - 0.5f, 0.0f);
    const int i_last    = min(i_last_lo + 1, in_size - 1);
    const int nrows     = i_last - i_first + 1;   // <= 10

    // Packed per-row table: (q0 bits, q1 bits, w0, w1) — one LDS.128 broadcast/row
    __shared__ __align__(16) float4 s_tab[RPB];
    if (tid < RPB) {
        const int r = rb + tid;
        float src = fmaxf((r + 0.5f) * scale - 0.5f, 0.0f);
        int   i0  = (int)src;
        float wr  = src - (float)i0;
        int   i1  = min(i0 + 1, in_size - 1);
        const float r0a = (float)((tx - tl) + i0);
        const float r1a = (float)((tx - tl) + i1);
        s_tab[tid] = make_float4(__int_as_float(i0 - i_first),
                                 __int_as_float(i1 - i_first),
                                 (1.0f - wr) * mask1d(r0a, txf, tlf),
                                 wr          * mask1d(r1a, txf, tlf));
    }
    __syncthreads();

    const float* __restrict__ inb  = in  + (size_t)b * (3 * CHS);
    float*       __restrict__ outb = out + (size_t)b * (3 * CHS);

    const float* p0 = inb + abs_first * IMG + c0;
    const float* p1 = inb + abs_first * IMG + c1;
    float*       ob = outb + rb * IMG + tid;

    // Triple-buffered register roll over source rows; 3 channels in parallel
    // (6 batched LDGs per new source row). All control flow is block-uniform.
    float va[3], vb[3], vc[3];
    #pragma unroll
    for (int ch = 0; ch < 3; ch++)
        va[ch] = fmaf(a0c, __ldg(p0 + ch * CHS), a1c * __ldg(p1 + ch * CHS));
    if (nrows > 1) {
        #pragma unroll
        for (int ch = 0; ch < 3; ch++)
            vb[ch] = fmaf(a0c, __ldg(p0 + ch * CHS + IMG), a1c * __ldg(p1 + ch * CHS + IMG));
    } else {
        #pragma unroll
        for (int ch = 0; ch < 3; ch++) vb[ch] = va[ch];
    }
    if (nrows > 2) {
        #pragma unroll
        for (int ch = 0; ch < 3; ch++)
            vc[ch] = fmaf(a0c, __ldg(p0 + ch * CHS + 2 * IMG), a1c * __ldg(p1 + ch * CHS + 2 * IMG));
    } else {
        #pragma unroll
        for (int ch = 0; ch < 3; ch++) vc[ch] = vb[ch];
    }

    int q = 0;
    #pragma unroll
    for (int r = 0; r < RPB; r++) {
        const float4 t  = s_tab[r];
        const int    q0 = __float_as_int(t.x);
        const int    q1 = __float_as_int(t.y);

        if (q0 != q) {                       // advance exactly one source row
            #pragma unroll
            for (int ch = 0; ch < 3; ch++) { va[ch] = vb[ch]; vb[ch] = vc[ch]; }
            if (q0 + 2 < nrows) {            // prefetch one row ahead
                const int o = (q0 + 2) * IMG;
                #pragma unroll
                for (int ch = 0; ch < 3; ch++)
                    vc[ch] = fmaf(a0c, __ldg(p0 + ch * CHS + o),
                                  a1c * __ldg(p1 + ch * CHS + o));
            }
            q = q0;
        }

        const bool two = (q1 != q0);         // uniform; false only at clamp edge
        #pragma unroll
        for (int ch = 0; ch < 3; ch++) {
            const float v1 = two ? vb[ch] : va[ch];
            __stcs(&ob[ch * CHS + r * IMG], fmaf(t.z, va[ch], t.w * v1));
        }
    }
}

extern "C" void kernel_launch(void* const* d_in, const int* in_sizes, int n_in,
                              void* d_out, int out_size) {
    const float* apn = (const float*)d_in[0];   // [256, 3]
    const float* in  = (const float*)d_in[1];   // [256, 3, 224, 224]
    float* out = (float*)d_out;                 // [256, 3, 224, 224]

    dim3 grid(IMG / RPB, 256);                  // (14 row-chunks, B)
    attention_crop_kernel<<<grid, THREADS>>>(apn, in, out);
}